// round 12
// baseline (speedup 1.0000x reference)
#include <cuda_runtime.h>
#include <cuda_bf16.h>
#include <math.h>

#define BB 2
#define TT 2048
#define DD 1024
#define HH 16
#define DK 64

typedef unsigned long long u64;
typedef unsigned int u32;

__device__ __forceinline__ void ldmx4(u32& r0, u32& r1, u32& r2, u32& r3, const void* p) {
    u32 addr = (u32)__cvta_generic_to_shared(p);
    asm volatile("ldmatrix.sync.aligned.m8n8.x4.shared.b16 {%0,%1,%2,%3},[%4];"
                 : "=r"(r0), "=r"(r1), "=r"(r2), "=r"(r3) : "r"(addr));
}
__device__ __forceinline__ void ldmx4t(u32& r0, u32& r1, u32& r2, u32& r3, const void* p) {
    u32 addr = (u32)__cvta_generic_to_shared(p);
    asm volatile("ldmatrix.sync.aligned.m8n8.x4.trans.shared.b16 {%0,%1,%2,%3},[%4];"
                 : "=r"(r0), "=r"(r1), "=r"(r2), "=r"(r3) : "r"(addr));
}
// NON-volatile: pure register function; lets ptxas software-pipeline HMMA chains.
__device__ __forceinline__ void mma16816(float* c, const u32* a, const u32* b) {
    asm("mma.sync.aligned.m16n8k16.row.col.f32.bf16.bf16.f32 "
        "{%0,%1,%2,%3},{%4,%5,%6,%7},{%8,%9},{%0,%1,%2,%3};"
        : "+f"(c[0]), "+f"(c[1]), "+f"(c[2]), "+f"(c[3])
        : "r"(a[0]), "r"(a[1]), "r"(a[2]), "r"(a[3]), "r"(b[0]), "r"(b[1]));
}
__device__ __forceinline__ u32 packbf(float lo, float hi) {
    u32 r; asm("cvt.rn.satfinite.bf16x2.f32 %0,%1,%2;" : "=r"(r) : "f"(hi), "f"(lo));
    return r;
}
__device__ __forceinline__ void cp16(u32 dst, const void* src) {
    asm volatile("cp.async.cg.shared.global [%0],[%1],16;" :: "r"(dst), "l"(src));
}
#define CP_COMMIT() asm volatile("cp.async.commit_group;")
#define CP_WAIT1()  asm volatile("cp.async.wait_group 1;")
#define CP_WAIT0()  asm volatile("cp.async.wait_group 0;")

// MUFU-free exp
__device__ __forceinline__ float fast_exp(float x) {
    float z = fmaxf(x * 1.4426950408889634f, -126.0f);
    float zi = z + 12582912.0f;
    float f = z - (zi - 12582912.0f);
    int n = __float_as_int(zi) - 0x4B400000;
    float p = 1.3333558e-3f;
    p = fmaf(p, f, 9.6181291e-3f);
    p = fmaf(p, f, 5.5504109e-2f);
    p = fmaf(p, f, 2.4022651e-1f);
    p = fmaf(p, f, 6.9314718e-1f);
    p = fmaf(p, f, 1.0f);
    return p * __int_as_float((n + 127) << 23);
}

// ---------------- scratch ----------------
__device__ __nv_bfloat16 g_I0h[BB*TT*DD], g_I0l[BB*TT*DD];
__device__ __nv_bfloat16 g_I1h[BB*TT*DD], g_I1l[BB*TT*DD];
__device__ __nv_bfloat16 g_I2h[BB*TT*DD], g_I2l[BB*TT*DD];
__device__ __nv_bfloat16 g_Wqh[DD*DD], g_Wql[DD*DD];
__device__ __nv_bfloat16 g_Wkh[DD*DD], g_Wkl[DD*DD];
__device__ __nv_bfloat16 g_Wvh[DD*DD], g_Wvl[DD*DD];
__device__ __nv_bfloat16 g_Woh[DD*DD], g_Wol[DD*DD];
__device__ __nv_bfloat16 g_Qh[BB*TT*DD], g_Ql[BB*TT*DD];
__device__ __nv_bfloat16 g_Kh[BB*TT*DD], g_Kl[BB*TT*DD];
__device__ __nv_bfloat16 g_Vh[BB*TT*DD], g_Vl[BB*TT*DD];
__device__ __nv_bfloat16 g_Ch[BB*TT*DD], g_Cl[BB*TT*DD];

// ---------------------------------------------------------------------------
// fused converts
// ---------------------------------------------------------------------------
__device__ __forceinline__ void split_store(const float4 v, u32* H, u32* L, int i) {
    u32 h0 = packbf(v.x, v.y), h1 = packbf(v.z, v.w);
    u32 l0 = packbf(v.x - __int_as_float(h0 << 16), v.y - __int_as_float(h0 & 0xFFFF0000u));
    u32 l1 = packbf(v.z - __int_as_float(h1 << 16), v.w - __int_as_float(h1 & 0xFFFF0000u));
    *(uint2*)&H[i * 2] = make_uint2(h0, h1);
    *(uint2*)&L[i * 2] = make_uint2(l0, l1);
}

__global__ __launch_bounds__(256) void convert_x3(
    const float4* __restrict__ X0, const float4* __restrict__ X1,
    const float4* __restrict__ X2,
    u32* __restrict__ H0, u32* __restrict__ L0,
    u32* __restrict__ H1, u32* __restrict__ L1,
    u32* __restrict__ H2, u32* __restrict__ L2)
{
    const int i = blockIdx.x * 256 + threadIdx.x;
    const int y = blockIdx.y;
    const float4* X = (y == 0) ? X0 : (y == 1) ? X1 : X2;
    u32* H = (y == 0) ? H0 : (y == 1) ? H1 : H2;
    u32* L = (y == 0) ? L0 : (y == 1) ? L1 : L2;
    split_store(X[i], H, L, i);
}

__global__ __launch_bounds__(256) void convert_w4(
    const float4* __restrict__ W0, const float4* __restrict__ W1,
    const float4* __restrict__ W2, const float4* __restrict__ W3,
    u32* __restrict__ H0, u32* __restrict__ L0,
    u32* __restrict__ H1, u32* __restrict__ L1,
    u32* __restrict__ H2, u32* __restrict__ L2,
    u32* __restrict__ H3, u32* __restrict__ L3)
{
    const int i = blockIdx.x * 256 + threadIdx.x;
    const int y = blockIdx.y;
    const float4* W = (y == 0) ? W0 : (y == 1) ? W1 : (y == 2) ? W2 : W3;
    u32* H = (y == 0) ? H0 : (y == 1) ? H1 : (y == 2) ? H2 : H3;
    u32* L = (y == 0) ? L0 : (y == 1) ? L1 : (y == 2) ? L2 : L3;
    split_store(W[i], H, L, i);
}

// ---------------------------------------------------------------------------
// GEMM: CTA tile 128x64, warp 32x32, BK=32, 3-stage cp.async, 2 CTAs/SM.
// ---------------------------------------------------------------------------
#define GW 40
#define OFF_AH 0
#define OFF_AL (128 * GW)
#define OFF_BH (256 * GW)
#define OFF_BL (256 * GW + 64 * GW)
#define GSTAGE (384 * GW)
#define GSMEM  (3 * GSTAGE * 2)          // 92160 B

struct GJob {
    const __nv_bfloat16 *Xh, *Xl, *Wh, *Wl;
    const float* bias;
    __nv_bfloat16 *Yh, *Yl;
    float oscale;
};

template<int MODE>
__device__ __forceinline__ void gemm_body(
    char* smraw,
    const __nv_bfloat16* __restrict__ Xh, const __nv_bfloat16* __restrict__ Xl,
    const __nv_bfloat16* __restrict__ Wh, const __nv_bfloat16* __restrict__ Wl,
    const float* __restrict__ bias, float* __restrict__ Yf,
    __nv_bfloat16* __restrict__ Yh, __nv_bfloat16* __restrict__ Yl, float oscale)
{
    __nv_bfloat16* SM = (__nv_bfloat16*)smraw;
    const u32 smb = (u32)__cvta_generic_to_shared(smraw);

    const int tid  = threadIdx.x;
    const int lane = tid & 31;
    const int warp = tid >> 5;
    const int wr = (warp & 3) * 32;
    const int wc = (warp >> 2) * 32;
    const int rowBase = blockIdx.y * 128;
    const int colBase = blockIdx.x * 64;

    const int ar  = tid >> 1;
    const int ac0 = (tid & 1) * 2;
    const int br  = tid & 63;
    const int bc  = tid >> 6;
    const __nv_bfloat16* xh = Xh + (u64)(rowBase + ar) * 1024;
    const __nv_bfloat16* xl = Xl + (u64)(rowBase + ar) * 1024;
    const __nv_bfloat16* wh = Wh + (u64)(colBase + br) * 1024;
    const __nv_bfloat16* wl = Wl + (u64)(colBase + br) * 1024;

    const int a_r = (lane & 15);
    const int a_k = (lane >> 4) * 8;
    const int b_r = ((lane >> 4) << 3) + (lane & 7);
    const int b_k = ((lane >> 3) & 1) * 8;

    float acc[2][4][4];
    #pragma unroll
    for (int mt = 0; mt < 2; mt++)
        #pragma unroll
        for (int nt = 0; nt < 4; nt++)
            #pragma unroll
            for (int q = 0; q < 4; q++) acc[mt][nt][q] = 0.f;

    auto issue = [&](int kt) {
        const u32 sb = smb + (u32)((kt % 3) * GSTAGE) * 2;
        const int k0 = kt * 32;
        #pragma unroll
        for (int c = 0; c < 2; c++) {
            cp16(sb + (u32)(OFF_AH + ar * GW + (ac0 + c) * 8) * 2, xh + k0 + (ac0 + c) * 8);
            cp16(sb + (u32)(OFF_AL + ar * GW + (ac0 + c) * 8) * 2, xl + k0 + (ac0 + c) * 8);
        }
        cp16(sb + (u32)(OFF_BH + br * GW + bc * 8) * 2, wh + k0 + bc * 8);
        cp16(sb + (u32)(OFF_BL + br * GW + bc * 8) * 2, wl + k0 + bc * 8);
        CP_COMMIT();
    };

    issue(0);
    issue(1);

    for (int kt = 0; kt < 32; kt++) {
        if (kt < 31) CP_WAIT1(); else CP_WAIT0();
        __syncthreads();
        if (kt + 2 < 32) issue(kt + 2);

        const __nv_bfloat16* Ah = SM + (kt % 3) * GSTAGE;
        const __nv_bfloat16* Al = Ah + OFF_AL;
        const __nv_bfloat16* Bh = Ah + OFF_BH;
        const __nv_bfloat16* Bl = Ah + OFF_BL;

        #pragma unroll
        for (int ks = 0; ks < 32; ks += 16) {
            u32 ah[2][4], al[2][4], bh[2][4], bl[2][4];
            #pragma unroll
            for (int mt = 0; mt < 2; mt++) {
                ldmx4(ah[mt][0], ah[mt][1], ah[mt][2], ah[mt][3],
                      &Ah[(wr + mt*16 + a_r) * GW + ks + a_k]);
                ldmx4(al[mt][0], al[mt][1], al[mt][2], al[mt][3],
                      &Al[(wr + mt*16 + a_r) * GW + ks + a_k]);
            }
            #pragma unroll
            for (int p = 0; p < 2; p++) {
                ldmx4(bh[p][0], bh[p][1], bh[p][2], bh[p][3],
                      &Bh[(wc + p*16 + b_r) * GW + ks + b_k]);
                ldmx4(bl[p][0], bl[p][1], bl[p][2], bl[p][3],
                      &Bl[(wc + p*16 + b_r) * GW + ks + b_k]);
            }
            // interleaved: all 8 (mt,nt) chains advance one product at a time
            #pragma unroll
            for (int mt = 0; mt < 2; mt++)
                #pragma unroll
                for (int nt = 0; nt < 4; nt++)
                    mma16816(acc[mt][nt], ah[mt], &bh[nt >> 1][(nt & 1) * 2]);
            #pragma unroll
            for (int mt = 0; mt < 2; mt++)
                #pragma unroll
                for (int nt = 0; nt < 4; nt++)
                    mma16816(acc[mt][nt], ah[mt], &bl[nt >> 1][(nt & 1) * 2]);
            #pragma unroll
            for (int mt = 0; mt < 2; mt++)
                #pragma unroll
                for (int nt = 0; nt < 4; nt++)
                    mma16816(acc[mt][nt], al[mt], &bh[nt >> 1][(nt & 1) * 2]);
        }
    }

    const int crow = rowBase + wr + (lane >> 2);
    const int ccol = colBase + wc + (lane & 3) * 2;
    #pragma unroll
    for (int mt = 0; mt < 2; mt++)
        #pragma unroll
        for (int nt = 0; nt < 4; nt++) {
            const int row = crow + mt * 16;
            const int col = ccol + (nt >> 1) * 16 + (nt & 1) * 8;
            const float b0 = bias[col], b1 = bias[col + 1];
            float y00 = acc[mt][nt][0] + b0, y01 = acc[mt][nt][1] + b1;
            float y10 = acc[mt][nt][2] + b0, y11 = acc[mt][nt][3] + b1;
            if (MODE == 0) {
                Yf[(u64)row * 1024 + col]           = y00;
                Yf[(u64)row * 1024 + col + 1]       = y01;
                Yf[(u64)(row + 8) * 1024 + col]     = y10;
                Yf[(u64)(row + 8) * 1024 + col + 1] = y11;
            } else {
                y00 *= oscale; y01 *= oscale; y10 *= oscale; y11 *= oscale;
                u32 h0 = packbf(y00, y01);
                u32 l0 = packbf(y00 - __int_as_float(h0 << 16),
                                y01 - __int_as_float(h0 & 0xFFFF0000u));
                u32 h1 = packbf(y10, y11);
                u32 l1 = packbf(y10 - __int_as_float(h1 << 16),
                                y11 - __int_as_float(h1 & 0xFFFF0000u));
                *(u32*)&Yh[(u64)row * 1024 + col]       = h0;
                *(u32*)&Yl[(u64)row * 1024 + col]       = l0;
                *(u32*)&Yh[(u64)(row + 8) * 1024 + col] = h1;
                *(u32*)&Yl[(u64)(row + 8) * 1024 + col] = l1;
            }
        }
}

__global__ __launch_bounds__(256, 2) void gemm_qkv_tc(GJob j0, GJob j1, GJob j2)
{
    extern __shared__ char smraw[];
    const GJob& j = (blockIdx.z == 0) ? j0 : (blockIdx.z == 1) ? j1 : j2;
    gemm_body<1>(smraw, j.Xh, j.Xl, j.Wh, j.Wl, j.bias, nullptr, j.Yh, j.Yl, j.oscale);
}

__global__ __launch_bounds__(256, 2) void gemm_out_tc(
    const __nv_bfloat16* __restrict__ Xh, const __nv_bfloat16* __restrict__ Xl,
    const __nv_bfloat16* __restrict__ Wh, const __nv_bfloat16* __restrict__ Wl,
    const float* __restrict__ bias, float* __restrict__ Yf)
{
    extern __shared__ char smraw[];
    gemm_body<0>(smraw, Xh, Xl, Wh, Wl, bias, Yf, nullptr, nullptr, 1.0f);
}

// ---------------------------------------------------------------------------
// Flash attention: 128 threads (4 warps), Q-tile 64, key-tile 64, 2-stage KV.
// ---------------------------------------------------------------------------
#define KST 72
#define FARR (64 * KST)
#define FSTAGE (4 * FARR)

__global__ __launch_bounds__(128, 2) void flash_attn_tc(
    const __nv_bfloat16* __restrict__ Qhg, const __nv_bfloat16* __restrict__ Qlg,
    const __nv_bfloat16* __restrict__ Khg, const __nv_bfloat16* __restrict__ Klg,
    const __nv_bfloat16* __restrict__ Vhg, const __nv_bfloat16* __restrict__ Vlg,
    const int* __restrict__ mask,
    __nv_bfloat16* __restrict__ Ch, __nv_bfloat16* __restrict__ Cl)
{
    extern __shared__ char smraw[];
    __nv_bfloat16* Qh_s = (__nv_bfloat16*)smraw;
    __nv_bfloat16* Ql_s = Qh_s + FARR;
    __nv_bfloat16* KV   = Ql_s + FARR;
    float* mb = (float*)(KV + 2 * FSTAGE);
    const u32 kvb = (u32)__cvta_generic_to_shared(KV);

    const int tid  = threadIdx.x;
    const int lane = tid & 31;
    const int warp = tid >> 5;
    const int wr   = warp * 16;
    const int q0 = blockIdx.x * 64;
    const int h  = blockIdx.y;
    const int b  = blockIdx.z;

    const int a_r = (lane & 15);
    const int a_k = (lane >> 4) * 8;
    const int b_r = ((lane >> 4) << 3) + (lane & 7);
    const int b_k = ((lane >> 3) & 1) * 8;
    const int v_r = (((lane >> 3) & 1) << 3) + (lane & 7);
    const int v_c = (lane >> 4) * 8;

    {
        const int row = tid >> 1;
        const int half = (tid & 1) * 32;
        const u64 gro = (u64)(b * TT + q0 + row) * DD + h * DK + half;
        #pragma unroll
        for (int c = 0; c < 4; c++) {
            *(uint4*)&Qh_s[row * KST + half + c * 8] = *(const uint4*)&Qhg[gro + c * 8];
            *(uint4*)&Ql_s[row * KST + half + c * 8] = *(const uint4*)&Qlg[gro + c * 8];
        }
    }
    __syncthreads();
    u32 qah[4][4], qal[4][4];
    #pragma unroll
    for (int ks = 0; ks < 4; ks++) {
        ldmx4(qah[ks][0], qah[ks][1], qah[ks][2], qah[ks][3],
              &Qh_s[(wr + a_r) * KST + ks * 16 + a_k]);
        ldmx4(qal[ks][0], qal[ks][1], qal[ks][2], qal[ks][3],
              &Ql_s[(wr + a_r) * KST + ks * 16 + a_k]);
    }

    const int la = warp;
    const int r0 = (tid & 31) * 2;
    const __nv_bfloat16* sp = (la == 0) ? Khg : (la == 1) ? Klg : (la == 2) ? Vhg : Vlg;
    const u32 dbase = kvb + (u32)(la * FARR + r0 * KST) * 2;

    auto issueKV = [&](int t, int buf) {
        const int s0 = t * 64;
        const __nv_bfloat16* sbase = sp + (u64)(b * TT + s0 + r0) * DD + h * DK;
        #pragma unroll
        for (int rr = 0; rr < 2; rr++)
            #pragma unroll
            for (int c = 0; c < 8; c++)
                cp16(dbase + (u32)(buf * FSTAGE + rr * KST + c * 8) * 2,
                     sbase + (u64)rr * DD + c * 8);
        if (tid < 64)
            mb[buf * 64 + tid] = (mask[b * TT + s0 + tid] != 0) ? 0.f : -1e30f;
        CP_COMMIT();
    };

    issueKV(0, 0);
    issueKV(1, 1);

    float m0 = -1e30f, m1 = -1e30f, l0 = 0.f, l1 = 0.f;
    float o[8][4];
    #pragma unroll
    for (int nt = 0; nt < 8; nt++)
        #pragma unroll
        for (int q = 0; q < 4; q++) o[nt][q] = 0.f;

    for (int t = 0; t < 32; t++) {
        if (t < 31) CP_WAIT1(); else CP_WAIT0();
        __syncthreads();
        const int buf = t & 1;
        const __nv_bfloat16* Khs = KV + buf * FSTAGE;
        const __nv_bfloat16* Kls = Khs + FARR;
        const __nv_bfloat16* Vhs = Kls + FARR;
        const __nv_bfloat16* Vls = Vhs + FARR;
        const float* mbp = mb + buf * 64;

        // ---- S = Qs @ K^T (interleaved chains) ----
        float s[8][4];
        #pragma unroll
        for (int nt = 0; nt < 8; nt++)
            #pragma unroll
            for (int q = 0; q < 4; q++) s[nt][q] = 0.f;

        #pragma unroll
        for (int np = 0; np < 4; np++) {
            #pragma unroll
            for (int ks = 0; ks < 4; ks++) {
                u32 bh[4], bl[4];
                ldmx4(bh[0], bh[1], bh[2], bh[3],
                      &Khs[(np*16 + b_r) * KST + ks*16 + b_k]);
                ldmx4(bl[0], bl[1], bl[2], bl[3],
                      &Kls[(np*16 + b_r) * KST + ks*16 + b_k]);
                mma16816(s[2*np],   qah[ks], &bh[0]);
                mma16816(s[2*np+1], qah[ks], &bh[2]);
                mma16816(s[2*np],   qal[ks], &bh[0]);
                mma16816(s[2*np+1], qal[ks], &bh[2]);
                mma16816(s[2*np],   qah[ks], &bl[0]);
                mma16816(s[2*np+1], qah[ks], &bl[2]);
            }
        }

        // ---- mask + online softmax ----
        float mx0 = m0, mx1 = m1;
        #pragma unroll
        for (int nt = 0; nt < 8; nt++) {
            float2 mbv = *(const float2*)&mbp[nt*8 + (lane & 3)*2];
            s[nt][0] += mbv.x; s[nt][1] += mbv.y;
            s[nt][2] += mbv.x; s[nt][3] += mbv.y;
            mx0 = fmaxf(mx0, fmaxf(s[nt][0], s[nt][1]));
            mx1 = fmaxf(mx1, fmaxf(s[nt][2], s[nt][3]));
        }
        mx0 = fmaxf(mx0, __shfl_xor_sync(0xffffffffu, mx0, 1));
        mx0 = fmaxf(mx0, __shfl_xor_sync(0xffffffffu, mx0, 2));
        mx1 = fmaxf(mx1, __shfl_xor_sync(0xffffffffu, mx1, 1));
        mx1 = fmaxf(mx1, __shfl_xor_sync(0xffffffffu, mx1, 2));
        const float sc0 = fast_exp(m0 - mx0);
        const float sc1 = fast_exp(m1 - mx1);
        m0 = mx0; m1 = mx1;
        float rs0 = 0.f, rs1 = 0.f;
        #pragma unroll
        for (int nt = 0; nt < 8; nt++) {
            s[nt][0] = fast_exp(s[nt][0] - mx0);
            s[nt][1] = fast_exp(s[nt][1] - mx0);
            s[nt][2] = fast_exp(s[nt][2] - mx1);
            s[nt][3] = fast_exp(s[nt][3] - mx1);
            rs0 += s[nt][0] + s[nt][1];
            rs1 += s[nt][2] + s[nt][3];
        }
        rs0 += __shfl_xor_sync(0xffffffffu, rs0, 1);
        rs0 += __shfl_xor_sync(0xffffffffu, rs0, 2);
        rs1 += __shfl_xor_sync(0xffffffffu, rs1, 1);
        rs1 += __shfl_xor_sync(0xffffffffu, rs1, 2);
        l0 = l0 * sc0 + rs0;
        l1 = l1 * sc1 + rs1;
        #pragma unroll
        for (int nt = 0; nt < 8; nt++) {
            o[nt][0] *= sc0; o[nt][1] *= sc0;
            o[nt][2] *= sc1; o[nt][3] *= sc1;
        }

        // ---- O += P @ V (interleaved chains) ----
        #pragma unroll
        for (int kc = 0; kc < 4; kc++) {
            u32 pah[4], pal[4];
            #pragma unroll
            for (int half = 0; half < 2; half++) {
                const float* spv = s[2*kc + half];
                u32 h0 = packbf(spv[0], spv[1]);
                u32 h1 = packbf(spv[2], spv[3]);
                pah[half*2 + 0] = h0;
                pah[half*2 + 1] = h1;
                pal[half*2 + 0] = packbf(spv[0] - __int_as_float(h0 << 16),
                                         spv[1] - __int_as_float(h0 & 0xFFFF0000u));
                pal[half*2 + 1] = packbf(spv[2] - __int_as_float(h1 << 16),
                                         spv[3] - __int_as_float(h1 & 0xFFFF0000u));
            }
            #pragma unroll
            for (int nb = 0; nb < 4; nb++) {
                u32 vh[4], vl[4];
                ldmx4t(vh[0], vh[1], vh[2], vh[3],
                       &Vhs[(kc*16 + v_r) * KST + nb*16 + v_c]);
                ldmx4t(vl[0], vl[1], vl[2], vl[3],
                       &Vls[(kc*16 + v_r) * KST + nb*16 + v_c]);
                mma16816(o[2*nb],   pah, &vh[0]);
                mma16816(o[2*nb+1], pah, &vh[2]);
                mma16816(o[2*nb],   pal, &vh[0]);
                mma16816(o[2*nb+1], pal, &vh[2]);
                mma16816(o[2*nb],   pah, &vl[0]);
                mma16816(o[2*nb+1], pah, &vl[2]);
            }
        }

        __syncthreads();
        if (t + 2 < 32) issueKV(t + 2, buf);
    }

    const float inv0 = 1.f / l0;
    const float inv1 = 1.f / l1;
    const int row0 = b * TT + q0 + wr + (lane >> 2);
    #pragma unroll
    for (int nt = 0; nt < 8; nt++) {
        const int dcol = h * DK + (nt >> 1) * 16 + (nt & 1) * 8 + (lane & 3) * 2;
        float y00 = o[nt][0] * inv0, y01 = o[nt][1] * inv0;
        float y10 = o[nt][2] * inv1, y11 = o[nt][3] * inv1;
        u32 h0 = packbf(y00, y01);
        u32 l0p = packbf(y00 - __int_as_float(h0 << 16),
                         y01 - __int_as_float(h0 & 0xFFFF0000u));
        u32 h1 = packbf(y10, y11);
        u32 l1p = packbf(y10 - __int_as_float(h1 << 16),
                         y11 - __int_as_float(h1 & 0xFFFF0000u));
        *(u32*)&Ch[(u64)row0 * DD + dcol]       = h0;
        *(u32*)&Cl[(u64)row0 * DD + dcol]       = l0p;
        *(u32*)&Ch[(u64)(row0 + 8) * DD + dcol] = h1;
        *(u32*)&Cl[(u64)(row0 + 8) * DD + dcol] = l1p;
    }
}

// ---------------------------------------------------------------------------
extern "C" void kernel_launch(void* const* d_in, const int* in_sizes, int n_in,
                              void* d_out, int out_size)
{
    const float* query = (const float*)d_in[0];
    const float* key   = (const float*)d_in[1];
    const float* value = (const float*)d_in[2];
    const int*   mask  = (const int*)d_in[3];
    const float* Wq = (const float*)d_in[4];
    const float* bq = (const float*)d_in[5];
    const float* Wk = (const float*)d_in[6];
    const float* bk = (const float*)d_in[7];
    const float* Wv = (const float*)d_in[8];
    const float* bv = (const float*)d_in[9];
    const float* Wo = (const float*)d_in[10];
    const float* bo = (const float*)d_in[11];
    float* out = (float*)d_out;

    __nv_bfloat16 *I0h,*I0l,*I1h,*I1l,*I2h,*I2l;
    __nv_bfloat16 *Wqh,*Wql,*Wkh,*Wkl,*Wvh,*Wvl,*Woh,*Wol;
    __nv_bfloat16 *Qh,*Ql,*Kh,*Kl,*Vh,*Vl,*Ch,*Cl;
    cudaGetSymbolAddress((void**)&I0h, g_I0h);  cudaGetSymbolAddress((void**)&I0l, g_I0l);
    cudaGetSymbolAddress((void**)&I1h, g_I1h);  cudaGetSymbolAddress((void**)&I1l, g_I1l);
    cudaGetSymbolAddress((void**)&I2h, g_I2h);  cudaGetSymbolAddress((void**)&I2l, g_I2l);
    cudaGetSymbolAddress((void**)&Wqh, g_Wqh);  cudaGetSymbolAddress((void**)&Wql, g_Wql);
    cudaGetSymbolAddress((void**)&Wkh, g_Wkh);  cudaGetSymbolAddress((void**)&Wkl, g_Wkl);
    cudaGetSymbolAddress((void**)&Wvh, g_Wvh);  cudaGetSymbolAddress((void**)&Wvl, g_Wvl);
    cudaGetSymbolAddress((void**)&Woh, g_Woh);  cudaGetSymbolAddress((void**)&Wol, g_Wol);
    cudaGetSymbolAddress((void**)&Qh, g_Qh);    cudaGetSymbolAddress((void**)&Ql, g_Ql);
    cudaGetSymbolAddress((void**)&Kh, g_Kh);    cudaGetSymbolAddress((void**)&Kl, g_Kl);
    cudaGetSymbolAddress((void**)&Vh, g_Vh);    cudaGetSymbolAddress((void**)&Vl, g_Vl);
    cudaGetSymbolAddress((void**)&Ch, g_Ch);    cudaGetSymbolAddress((void**)&Cl, g_Cl);

    const int fsmem = (2*FARR + 2*FSTAGE) * 2 + 2*64*4;  // 92672 B
    static bool attrDone = false;
    if (!attrDone) {
        cudaFuncSetAttribute(gemm_qkv_tc, cudaFuncAttributeMaxDynamicSharedMemorySize, GSMEM);
        cudaFuncSetAttribute(gemm_out_tc, cudaFuncAttributeMaxDynamicSharedMemorySize, GSMEM);
        cudaFuncSetAttribute(flash_attn_tc, cudaFuncAttributeMaxDynamicSharedMemorySize, fsmem);
        attrDone = true;
    }

    const int nW4 = DD * DD / 4;
    const int nX4 = BB * TT * DD / 4;

    convert_w4<<<dim3(nW4 / 256, 4), 256>>>(
        (const float4*)Wq, (const float4*)Wk, (const float4*)Wv, (const float4*)Wo,
        (u32*)Wqh, (u32*)Wql, (u32*)Wkh, (u32*)Wkl,
        (u32*)Wvh, (u32*)Wvl, (u32*)Woh, (u32*)Wol);
    convert_x3<<<dim3(nX4 / 256, 3), 256>>>(
        (const float4*)query, (const float4*)key, (const float4*)value,
        (u32*)I0h, (u32*)I0l, (u32*)I1h, (u32*)I1l, (u32*)I2h, (u32*)I2l);

    GJob jq = { I0h, I0l, Wqh, Wql, bq, Qh, Ql, 0.125f };
    GJob jk = { I1h, I1l, Wkh, Wkl, bk, Kh, Kl, 1.0f };
    GJob jv = { I2h, I2l, Wvh, Wvl, bv, Vh, Vl, 1.0f };
    gemm_qkv_tc<<<dim3(16, 32, 3), 256, GSMEM>>>(jq, jk, jv);

    dim3 fgrid(TT / 64, HH, BB);          // (32, 16, 2) = 1024 CTAs
    flash_attn_tc<<<fgrid, 128, fsmem>>>(Qh, Ql, Kh, Kl, Vh, Vl, mask, Ch, Cl);

    gemm_out_tc<<<dim3(16, 32, 1), 256, GSMEM>>>(Ch, Cl, Woh, Wol, bo, out);
}

// round 14
// speedup vs baseline: 1.0315x; 1.0315x over previous
#include <cuda_runtime.h>
#include <cuda_bf16.h>
#include <math.h>

#define BB 2
#define TT 2048
#define DD 1024
#define HH 16
#define DK 64

typedef unsigned long long u64;
typedef unsigned int u32;

__device__ __forceinline__ void ldmx4(u32& r0, u32& r1, u32& r2, u32& r3, const void* p) {
    u32 addr = (u32)__cvta_generic_to_shared(p);
    asm volatile("ldmatrix.sync.aligned.m8n8.x4.shared.b16 {%0,%1,%2,%3},[%4];"
                 : "=r"(r0), "=r"(r1), "=r"(r2), "=r"(r3) : "r"(addr));
}
__device__ __forceinline__ void ldmx4t(u32& r0, u32& r1, u32& r2, u32& r3, const void* p) {
    u32 addr = (u32)__cvta_generic_to_shared(p);
    asm volatile("ldmatrix.sync.aligned.m8n8.x4.trans.shared.b16 {%0,%1,%2,%3},[%4];"
                 : "=r"(r0), "=r"(r1), "=r"(r2), "=r"(r3) : "r"(addr));
}
// NON-volatile: pure register function; ptxas may software-pipeline HMMA chains.
__device__ __forceinline__ void mma16816(float* c, const u32* a, const u32* b) {
    asm("mma.sync.aligned.m16n8k16.row.col.f32.bf16.bf16.f32 "
        "{%0,%1,%2,%3},{%4,%5,%6,%7},{%8,%9},{%0,%1,%2,%3};"
        : "+f"(c[0]), "+f"(c[1]), "+f"(c[2]), "+f"(c[3])
        : "r"(a[0]), "r"(a[1]), "r"(a[2]), "r"(a[3]), "r"(b[0]), "r"(b[1]));
}
__device__ __forceinline__ u32 packbf(float lo, float hi) {
    u32 r; asm("cvt.rn.satfinite.bf16x2.f32 %0,%1,%2;" : "=r"(r) : "f"(hi), "f"(lo));
    return r;
}
__device__ __forceinline__ void cp16(u32 dst, const void* src) {
    asm volatile("cp.async.cg.shared.global [%0],[%1],16;" :: "r"(dst), "l"(src));
}
#define CP_COMMIT() asm volatile("cp.async.commit_group;")
#define CP_WAIT1()  asm volatile("cp.async.wait_group 1;")
#define CP_WAIT0()  asm volatile("cp.async.wait_group 0;")

// MUFU-free exp
__device__ __forceinline__ float fast_exp(float x) {
    float z = fmaxf(x * 1.4426950408889634f, -126.0f);
    float zi = z + 12582912.0f;
    float f = z - (zi - 12582912.0f);
    int n = __float_as_int(zi) - 0x4B400000;
    float p = 1.3333558e-3f;
    p = fmaf(p, f, 9.6181291e-3f);
    p = fmaf(p, f, 5.5504109e-2f);
    p = fmaf(p, f, 2.4022651e-1f);
    p = fmaf(p, f, 6.9314718e-1f);
    p = fmaf(p, f, 1.0f);
    return p * __int_as_float((n + 127) << 23);
}

// ---------------- scratch ----------------
__device__ __nv_bfloat16 g_I0h[BB*TT*DD], g_I0l[BB*TT*DD];
__device__ __nv_bfloat16 g_I1h[BB*TT*DD], g_I1l[BB*TT*DD];
__device__ __nv_bfloat16 g_I2h[BB*TT*DD], g_I2l[BB*TT*DD];
__device__ __nv_bfloat16 g_Wqh[DD*DD], g_Wql[DD*DD];
__device__ __nv_bfloat16 g_Wkh[DD*DD], g_Wkl[DD*DD];
__device__ __nv_bfloat16 g_Wvh[DD*DD], g_Wvl[DD*DD];
__device__ __nv_bfloat16 g_Woh[DD*DD], g_Wol[DD*DD];
__device__ __nv_bfloat16 g_Qh[BB*TT*DD], g_Ql[BB*TT*DD];
__device__ __nv_bfloat16 g_Kh[BB*TT*DD], g_Kl[BB*TT*DD];
__device__ __nv_bfloat16 g_Vh[BB*TT*DD], g_Vl[BB*TT*DD];
__device__ __nv_bfloat16 g_Ch[BB*TT*DD], g_Cl[BB*TT*DD];

// ---------------------------------------------------------------------------
// fused converts
// ---------------------------------------------------------------------------
__device__ __forceinline__ void split_store(const float4 v, u32* H, u32* L, int i) {
    u32 h0 = packbf(v.x, v.y), h1 = packbf(v.z, v.w);
    u32 l0 = packbf(v.x - __int_as_float(h0 << 16), v.y - __int_as_float(h0 & 0xFFFF0000u));
    u32 l1 = packbf(v.z - __int_as_float(h1 << 16), v.w - __int_as_float(h1 & 0xFFFF0000u));
    *(uint2*)&H[i * 2] = make_uint2(h0, h1);
    *(uint2*)&L[i * 2] = make_uint2(l0, l1);
}

__global__ __launch_bounds__(256) void convert_x3(
    const float4* __restrict__ X0, const float4* __restrict__ X1,
    const float4* __restrict__ X2,
    u32* __restrict__ H0, u32* __restrict__ L0,
    u32* __restrict__ H1, u32* __restrict__ L1,
    u32* __restrict__ H2, u32* __restrict__ L2)
{
    const int i = blockIdx.x * 256 + threadIdx.x;
    const int y = blockIdx.y;
    const float4* X = (y == 0) ? X0 : (y == 1) ? X1 : X2;
    u32* H = (y == 0) ? H0 : (y == 1) ? H1 : H2;
    u32* L = (y == 0) ? L0 : (y == 1) ? L1 : L2;
    split_store(X[i], H, L, i);
}

__global__ __launch_bounds__(256) void convert_w4(
    const float4* __restrict__ W0, const float4* __restrict__ W1,
    const float4* __restrict__ W2, const float4* __restrict__ W3,
    u32* __restrict__ H0, u32* __restrict__ L0,
    u32* __restrict__ H1, u32* __restrict__ L1,
    u32* __restrict__ H2, u32* __restrict__ L2,
    u32* __restrict__ H3, u32* __restrict__ L3)
{
    const int i = blockIdx.x * 256 + threadIdx.x;
    const int y = blockIdx.y;
    const float4* W = (y == 0) ? W0 : (y == 1) ? W1 : (y == 2) ? W2 : W3;
    u32* H = (y == 0) ? H0 : (y == 1) ? H1 : (y == 2) ? H2 : H3;
    u32* L = (y == 0) ? L0 : (y == 1) ? L1 : (y == 2) ? L2 : L3;
    split_store(W[i], H, L, i);
}

// ---------------------------------------------------------------------------
// GEMM: CTA tile 128x64, warp 32x32, BK=32, 3-stage cp.async, 2 CTAs/SM.
// (unchanged from R12)
// ---------------------------------------------------------------------------
#define GW 40
#define OFF_AH 0
#define OFF_AL (128 * GW)
#define OFF_BH (256 * GW)
#define OFF_BL (256 * GW + 64 * GW)
#define GSTAGE (384 * GW)
#define GSMEM  (3 * GSTAGE * 2)          // 92160 B

struct GJob {
    const __nv_bfloat16 *Xh, *Xl, *Wh, *Wl;
    const float* bias;
    __nv_bfloat16 *Yh, *Yl;
    float oscale;
};

template<int MODE>
__device__ __forceinline__ void gemm_body(
    char* smraw,
    const __nv_bfloat16* __restrict__ Xh, const __nv_bfloat16* __restrict__ Xl,
    const __nv_bfloat16* __restrict__ Wh, const __nv_bfloat16* __restrict__ Wl,
    const float* __restrict__ bias, float* __restrict__ Yf,
    __nv_bfloat16* __restrict__ Yh, __nv_bfloat16* __restrict__ Yl, float oscale)
{
    __nv_bfloat16* SM = (__nv_bfloat16*)smraw;
    const u32 smb = (u32)__cvta_generic_to_shared(smraw);

    const int tid  = threadIdx.x;
    const int lane = tid & 31;
    const int warp = tid >> 5;
    const int wr = (warp & 3) * 32;
    const int wc = (warp >> 2) * 32;
    const int rowBase = blockIdx.y * 128;
    const int colBase = blockIdx.x * 64;

    const int ar  = tid >> 1;
    const int ac0 = (tid & 1) * 2;
    const int br  = tid & 63;
    const int bc  = tid >> 6;
    const __nv_bfloat16* xh = Xh + (u64)(rowBase + ar) * 1024;
    const __nv_bfloat16* xl = Xl + (u64)(rowBase + ar) * 1024;
    const __nv_bfloat16* wh = Wh + (u64)(colBase + br) * 1024;
    const __nv_bfloat16* wl = Wl + (u64)(colBase + br) * 1024;

    const int a_r = (lane & 15);
    const int a_k = (lane >> 4) * 8;
    const int b_r = ((lane >> 4) << 3) + (lane & 7);
    const int b_k = ((lane >> 3) & 1) * 8;

    float acc[2][4][4];
    #pragma unroll
    for (int mt = 0; mt < 2; mt++)
        #pragma unroll
        for (int nt = 0; nt < 4; nt++)
            #pragma unroll
            for (int q = 0; q < 4; q++) acc[mt][nt][q] = 0.f;

    auto issue = [&](int kt) {
        const u32 sb = smb + (u32)((kt % 3) * GSTAGE) * 2;
        const int k0 = kt * 32;
        #pragma unroll
        for (int c = 0; c < 2; c++) {
            cp16(sb + (u32)(OFF_AH + ar * GW + (ac0 + c) * 8) * 2, xh + k0 + (ac0 + c) * 8);
            cp16(sb + (u32)(OFF_AL + ar * GW + (ac0 + c) * 8) * 2, xl + k0 + (ac0 + c) * 8);
        }
        cp16(sb + (u32)(OFF_BH + br * GW + bc * 8) * 2, wh + k0 + bc * 8);
        cp16(sb + (u32)(OFF_BL + br * GW + bc * 8) * 2, wl + k0 + bc * 8);
        CP_COMMIT();
    };

    issue(0);
    issue(1);

    for (int kt = 0; kt < 32; kt++) {
        if (kt < 31) CP_WAIT1(); else CP_WAIT0();
        __syncthreads();
        if (kt + 2 < 32) issue(kt + 2);

        const __nv_bfloat16* Ah = SM + (kt % 3) * GSTAGE;
        const __nv_bfloat16* Al = Ah + OFF_AL;
        const __nv_bfloat16* Bh = Ah + OFF_BH;
        const __nv_bfloat16* Bl = Ah + OFF_BL;

        #pragma unroll
        for (int ks = 0; ks < 32; ks += 16) {
            u32 ah[2][4], al[2][4], bh[2][4], bl[2][4];
            #pragma unroll
            for (int mt = 0; mt < 2; mt++) {
                ldmx4(ah[mt][0], ah[mt][1], ah[mt][2], ah[mt][3],
                      &Ah[(wr + mt*16 + a_r) * GW + ks + a_k]);
                ldmx4(al[mt][0], al[mt][1], al[mt][2], al[mt][3],
                      &Al[(wr + mt*16 + a_r) * GW + ks + a_k]);
            }
            #pragma unroll
            for (int p = 0; p < 2; p++) {
                ldmx4(bh[p][0], bh[p][1], bh[p][2], bh[p][3],
                      &Bh[(wc + p*16 + b_r) * GW + ks + b_k]);
                ldmx4(bl[p][0], bl[p][1], bl[p][2], bl[p][3],
                      &Bl[(wc + p*16 + b_r) * GW + ks + b_k]);
            }
            #pragma unroll
            for (int mt = 0; mt < 2; mt++)
                #pragma unroll
                for (int nt = 0; nt < 4; nt++)
                    mma16816(acc[mt][nt], ah[mt], &bh[nt >> 1][(nt & 1) * 2]);
            #pragma unroll
            for (int mt = 0; mt < 2; mt++)
                #pragma unroll
                for (int nt = 0; nt < 4; nt++)
                    mma16816(acc[mt][nt], ah[mt], &bl[nt >> 1][(nt & 1) * 2]);
            #pragma unroll
            for (int mt = 0; mt < 2; mt++)
                #pragma unroll
                for (int nt = 0; nt < 4; nt++)
                    mma16816(acc[mt][nt], al[mt], &bh[nt >> 1][(nt & 1) * 2]);
        }
    }

    const int crow = rowBase + wr + (lane >> 2);
    const int ccol = colBase + wc + (lane & 3) * 2;
    #pragma unroll
    for (int mt = 0; mt < 2; mt++)
        #pragma unroll
        for (int nt = 0; nt < 4; nt++) {
            const int row = crow + mt * 16;
            const int col = ccol + (nt >> 1) * 16 + (nt & 1) * 8;
            const float b0 = bias[col], b1 = bias[col + 1];
            float y00 = acc[mt][nt][0] + b0, y01 = acc[mt][nt][1] + b1;
            float y10 = acc[mt][nt][2] + b0, y11 = acc[mt][nt][3] + b1;
            if (MODE == 0) {
                Yf[(u64)row * 1024 + col]           = y00;
                Yf[(u64)row * 1024 + col + 1]       = y01;
                Yf[(u64)(row + 8) * 1024 + col]     = y10;
                Yf[(u64)(row + 8) * 1024 + col + 1] = y11;
            } else {
                y00 *= oscale; y01 *= oscale; y10 *= oscale; y11 *= oscale;
                u32 h0 = packbf(y00, y01);
                u32 l0 = packbf(y00 - __int_as_float(h0 << 16),
                                y01 - __int_as_float(h0 & 0xFFFF0000u));
                u32 h1 = packbf(y10, y11);
                u32 l1 = packbf(y10 - __int_as_float(h1 << 16),
                                y11 - __int_as_float(h1 & 0xFFFF0000u));
                *(u32*)&Yh[(u64)row * 1024 + col]       = h0;
                *(u32*)&Yl[(u64)row * 1024 + col]       = l0;
                *(u32*)&Yh[(u64)(row + 8) * 1024 + col] = h1;
                *(u32*)&Yl[(u64)(row + 8) * 1024 + col] = l1;
            }
        }
}

__global__ __launch_bounds__(256, 2) void gemm_qkv_tc(GJob j0, GJob j1, GJob j2)
{
    extern __shared__ char smraw[];
    const GJob& j = (blockIdx.z == 0) ? j0 : (blockIdx.z == 1) ? j1 : j2;
    gemm_body<1>(smraw, j.Xh, j.Xl, j.Wh, j.Wl, j.bias, nullptr, j.Yh, j.Yl, j.oscale);
}

__global__ __launch_bounds__(256, 2) void gemm_out_tc(
    const __nv_bfloat16* __restrict__ Xh, const __nv_bfloat16* __restrict__ Xl,
    const __nv_bfloat16* __restrict__ Wh, const __nv_bfloat16* __restrict__ Wl,
    const float* __restrict__ bias, float* __restrict__ Yf)
{
    extern __shared__ char smraw[];
    gemm_body<0>(smraw, Xh, Xl, Wh, Wl, bias, Yf, nullptr, nullptr, 1.0f);
}

// ---------------------------------------------------------------------------
// Flash attention: 256 threads (8 warps), Q-tile 128, key-tile 64, 2-stage KV,
// 2 CTAs/SM (4 warps/SMSP from two phase-drifting CTAs).
// ---------------------------------------------------------------------------
#define KST 72
#define QARR (128 * KST)                // Q array (128 rows)
#define FARR (64 * KST)                 // K/V array (64 rows)
#define FSTAGE (4 * FARR)               // Kh,Kl,Vh,Vl per stage

__global__ __launch_bounds__(256, 2) void flash_attn_tc(
    const __nv_bfloat16* __restrict__ Qhg, const __nv_bfloat16* __restrict__ Qlg,
    const __nv_bfloat16* __restrict__ Khg, const __nv_bfloat16* __restrict__ Klg,
    const __nv_bfloat16* __restrict__ Vhg, const __nv_bfloat16* __restrict__ Vlg,
    const int* __restrict__ mask,
    __nv_bfloat16* __restrict__ Ch, __nv_bfloat16* __restrict__ Cl)
{
    extern __shared__ char smraw[];
    __nv_bfloat16* Qh_s = (__nv_bfloat16*)smraw;
    __nv_bfloat16* Ql_s = Qh_s + QARR;
    __nv_bfloat16* KV   = Ql_s + QARR;
    float* mb = (float*)(KV + 2 * FSTAGE);
    const u32 kvb = (u32)__cvta_generic_to_shared(KV);

    const int tid  = threadIdx.x;
    const int lane = tid & 31;
    const int warp = tid >> 5;       // 0..7
    const int wr   = warp * 16;      // q-row base (0..112)
    const int q0 = blockIdx.x * 128;
    const int h  = blockIdx.y;
    const int b  = blockIdx.z;

    const int a_r = (lane & 15);
    const int a_k = (lane >> 4) * 8;
    const int b_r = ((lane >> 4) << 3) + (lane & 7);
    const int b_k = ((lane >> 3) & 1) * 8;
    const int v_r = (((lane >> 3) & 1) << 3) + (lane & 7);
    const int v_c = (lane >> 4) * 8;

    // Q staging: 128 rows, 256 threads (2 threads/row)
    {
        const int row = tid >> 1;
        const int half = (tid & 1) * 32;
        const u64 gro = (u64)(b * TT + q0 + row) * DD + h * DK + half;
        #pragma unroll
        for (int c = 0; c < 4; c++) {
            *(uint4*)&Qh_s[row * KST + half + c * 8] = *(const uint4*)&Qhg[gro + c * 8];
            *(uint4*)&Ql_s[row * KST + half + c * 8] = *(const uint4*)&Qlg[gro + c * 8];
        }
    }
    __syncthreads();
    u32 qah[4][4], qal[4][4];
    #pragma unroll
    for (int ks = 0; ks < 4; ks++) {
        ldmx4(qah[ks][0], qah[ks][1], qah[ks][2], qah[ks][3],
              &Qh_s[(wr + a_r) * KST + ks * 16 + a_k]);
        ldmx4(qal[ks][0], qal[ks][1], qal[ks][2], qal[ks][3],
              &Ql_s[(wr + a_r) * KST + ks * 16 + a_k]);
    }

    // KV cp.async: 64 threads per array; 1 row x 8 chunks per thread
    const int la = tid >> 6;                 // 0:Kh 1:Kl 2:Vh 3:Vl
    const int r0 = tid & 63;                 // row 0..63
    const __nv_bfloat16* sp = (la == 0) ? Khg : (la == 1) ? Klg : (la == 2) ? Vhg : Vlg;
    const u32 dbase = kvb + (u32)(la * FARR + r0 * KST) * 2;

    auto issueKV = [&](int t, int buf) {
        const int s0 = t * 64;
        const __nv_bfloat16* sbase = sp + (u64)(b * TT + s0 + r0) * DD + h * DK;
        #pragma unroll
        for (int c = 0; c < 8; c++)
            cp16(dbase + (u32)(buf * FSTAGE + c * 8) * 2, sbase + c * 8);
        if (tid < 64)
            mb[buf * 64 + tid] = (mask[b * TT + s0 + tid] != 0) ? 0.f : -1e30f;
        CP_COMMIT();
    };

    issueKV(0, 0);
    issueKV(1, 1);

    float m0 = -1e30f, m1 = -1e30f, l0 = 0.f, l1 = 0.f;
    float o[8][4];
    #pragma unroll
    for (int nt = 0; nt < 8; nt++)
        #pragma unroll
        for (int q = 0; q < 4; q++) o[nt][q] = 0.f;

    for (int t = 0; t < 32; t++) {
        if (t < 31) CP_WAIT1(); else CP_WAIT0();
        __syncthreads();
        const int buf = t & 1;
        const __nv_bfloat16* Khs = KV + buf * FSTAGE;
        const __nv_bfloat16* Kls = Khs + FARR;
        const __nv_bfloat16* Vhs = Kls + FARR;
        const __nv_bfloat16* Vls = Vhs + FARR;
        const float* mbp = mb + buf * 64;

        // ---- S = Qs @ K^T (64 keys) ----
        float s[8][4];
        #pragma unroll
        for (int nt = 0; nt < 8; nt++)
            #pragma unroll
            for (int q = 0; q < 4; q++) s[nt][q] = 0.f;

        #pragma unroll
        for (int np = 0; np < 4; np++) {
            #pragma unroll
            for (int ks = 0; ks < 4; ks++) {
                u32 bh[4], bl[4];
                ldmx4(bh[0], bh[1], bh[2], bh[3],
                      &Khs[(np*16 + b_r) * KST + ks*16 + b_k]);
                ldmx4(bl[0], bl[1], bl[2], bl[3],
                      &Kls[(np*16 + b_r) * KST + ks*16 + b_k]);
                mma16816(s[2*np],   qah[ks], &bh[0]);
                mma16816(s[2*np+1], qah[ks], &bh[2]);
                mma16816(s[2*np],   qal[ks], &bh[0]);
                mma16816(s[2*np+1], qal[ks], &bh[2]);
                mma16816(s[2*np],   qah[ks], &bl[0]);
                mma16816(s[2*np+1], qah[ks], &bl[2]);
            }
        }

        // ---- mask + online softmax ----
        float mx0 = m0, mx1 = m1;
        #pragma unroll
        for (int nt = 0; nt < 8; nt++) {
            float2 mbv = *(const float2*)&mbp[nt*8 + (lane & 3)*2];
            s[nt][0] += mbv.x; s[nt][1] += mbv.y;
            s[nt][2] += mbv.x; s[nt][3] += mbv.y;
            mx0 = fmaxf(mx0, fmaxf(s[nt][0], s[nt][1]));
            mx1 = fmaxf(mx1, fmaxf(s[nt][2], s[nt][3]));
        }
        mx0 = fmaxf(mx0, __shfl_xor_sync(0xffffffffu, mx0, 1));
        mx0 = fmaxf(mx0, __shfl_xor_sync(0xffffffffu, mx0, 2));
        mx1 = fmaxf(mx1, __shfl_xor_sync(0xffffffffu, mx1, 1));
        mx1 = fmaxf(mx1, __shfl_xor_sync(0xffffffffu, mx1, 2));
        const float sc0 = fast_exp(m0 - mx0);
        const float sc1 = fast_exp(m1 - mx1);
        m0 = mx0; m1 = mx1;
        float rs0 = 0.f, rs1 = 0.f;
        #pragma unroll
        for (int nt = 0; nt < 8; nt++) {
            s[nt][0] = fast_exp(s[nt][0] - mx0);
            s[nt][1] = fast_exp(s[nt][1] - mx0);
            s[nt][2] = fast_exp(s[nt][2] - mx1);
            s[nt][3] = fast_exp(s[nt][3] - mx1);
            rs0 += s[nt][0] + s[nt][1];
            rs1 += s[nt][2] + s[nt][3];
        }
        rs0 += __shfl_xor_sync(0xffffffffu, rs0, 1);
        rs0 += __shfl_xor_sync(0xffffffffu, rs0, 2);
        rs1 += __shfl_xor_sync(0xffffffffu, rs1, 1);
        rs1 += __shfl_xor_sync(0xffffffffu, rs1, 2);
        l0 = l0 * sc0 + rs0;
        l1 = l1 * sc1 + rs1;
        #pragma unroll
        for (int nt = 0; nt < 8; nt++) {
            o[nt][0] *= sc0; o[nt][1] *= sc0;
            o[nt][2] *= sc1; o[nt][3] *= sc1;
        }

        // ---- O += P @ V (64 keys) ----
        #pragma unroll
        for (int kc = 0; kc < 4; kc++) {
            u32 pah[4], pal[4];
            #pragma unroll
            for (int half = 0; half < 2; half++) {
                const float* spv = s[2*kc + half];
                u32 h0 = packbf(spv[0], spv[1]);
                u32 h1 = packbf(spv[2], spv[3]);
                pah[half*2 + 0] = h0;
                pah[half*2 + 1] = h1;
                pal[half*2 + 0] = packbf(spv[0] - __int_as_float(h0 << 16),
                                         spv[1] - __int_as_float(h0 & 0xFFFF0000u));
                pal[half*2 + 1] = packbf(spv[2] - __int_as_float(h1 << 16),
                                         spv[3] - __int_as_float(h1 & 0xFFFF0000u));
            }
            #pragma unroll
            for (int nb = 0; nb < 4; nb++) {
                u32 vh[4], vl[4];
                ldmx4t(vh[0], vh[1], vh[2], vh[3],
                       &Vhs[(kc*16 + v_r) * KST + nb*16 + v_c]);
                ldmx4t(vl[0], vl[1], vl[2], vl[3],
                       &Vls[(kc*16 + v_r) * KST + nb*16 + v_c]);
                mma16816(o[2*nb],   pah, &vh[0]);
                mma16816(o[2*nb+1], pah, &vh[2]);
                mma16816(o[2*nb],   pal, &vh[0]);
                mma16816(o[2*nb+1], pal, &vh[2]);
                mma16816(o[2*nb],   pah, &vl[0]);
                mma16816(o[2*nb+1], pah, &vl[2]);
            }
        }

        __syncthreads();
        if (t + 2 < 32) issueKV(t + 2, buf);
    }

    const float inv0 = 1.f / l0;
    const float inv1 = 1.f / l1;
    const int row0 = b * TT + q0 + wr + (lane >> 2);
    #pragma unroll
    for (int nt = 0; nt < 8; nt++) {
        const int dcol = h * DK + (nt >> 1) * 16 + (nt & 1) * 8 + (lane & 3) * 2;
        float y00 = o[nt][0] * inv0, y01 = o[nt][1] * inv0;
        float y10 = o[nt][2] * inv1, y11 = o[nt][3] * inv1;
        u32 h0 = packbf(y00, y01);
        u32 l0p = packbf(y00 - __int_as_float(h0 << 16),
                         y01 - __int_as_float(h0 & 0xFFFF0000u));
        u32 h1 = packbf(y10, y11);
        u32 l1p = packbf(y10 - __int_as_float(h1 << 16),
                         y11 - __int_as_float(h1 & 0xFFFF0000u));
        *(u32*)&Ch[(u64)row0 * DD + dcol]       = h0;
        *(u32*)&Cl[(u64)row0 * DD + dcol]       = l0p;
        *(u32*)&Ch[(u64)(row0 + 8) * DD + dcol] = h1;
        *(u32*)&Cl[(u64)(row0 + 8) * DD + dcol] = l1p;
    }
}

// ---------------------------------------------------------------------------
extern "C" void kernel_launch(void* const* d_in, const int* in_sizes, int n_in,
                              void* d_out, int out_size)
{
    const float* query = (const float*)d_in[0];
    const float* key   = (const float*)d_in[1];
    const float* value = (const float*)d_in[2];
    const int*   mask  = (const int*)d_in[3];
    const float* Wq = (const float*)d_in[4];
    const float* bq = (const float*)d_in[5];
    const float* Wk = (const float*)d_in[6];
    const float* bk = (const float*)d_in[7];
    const float* Wv = (const float*)d_in[8];
    const float* bv = (const float*)d_in[9];
    const float* Wo = (const float*)d_in[10];
    const float* bo = (const float*)d_in[11];
    float* out = (float*)d_out;

    __nv_bfloat16 *I0h,*I0l,*I1h,*I1l,*I2h,*I2l;
    __nv_bfloat16 *Wqh,*Wql,*Wkh,*Wkl,*Wvh,*Wvl,*Woh,*Wol;
    __nv_bfloat16 *Qh,*Ql,*Kh,*Kl,*Vh,*Vl,*Ch,*Cl;
    cudaGetSymbolAddress((void**)&I0h, g_I0h);  cudaGetSymbolAddress((void**)&I0l, g_I0l);
    cudaGetSymbolAddress((void**)&I1h, g_I1h);  cudaGetSymbolAddress((void**)&I1l, g_I1l);
    cudaGetSymbolAddress((void**)&I2h, g_I2h);  cudaGetSymbolAddress((void**)&I2l, g_I2l);
    cudaGetSymbolAddress((void**)&Wqh, g_Wqh);  cudaGetSymbolAddress((void**)&Wql, g_Wql);
    cudaGetSymbolAddress((void**)&Wkh, g_Wkh);  cudaGetSymbolAddress((void**)&Wkl, g_Wkl);
    cudaGetSymbolAddress((void**)&Wvh, g_Wvh);  cudaGetSymbolAddress((void**)&Wvl, g_Wvl);
    cudaGetSymbolAddress((void**)&Woh, g_Woh);  cudaGetSymbolAddress((void**)&Wol, g_Wol);
    cudaGetSymbolAddress((void**)&Qh, g_Qh);    cudaGetSymbolAddress((void**)&Ql, g_Ql);
    cudaGetSymbolAddress((void**)&Kh, g_Kh);    cudaGetSymbolAddress((void**)&Kl, g_Kl);
    cudaGetSymbolAddress((void**)&Vh, g_Vh);    cudaGetSymbolAddress((void**)&Vl, g_Vl);
    cudaGetSymbolAddress((void**)&Ch, g_Ch);    cudaGetSymbolAddress((void**)&Cl, g_Cl);

    const int fsmem = (2*QARR + 2*FSTAGE) * 2 + 2*64*4;  // 111,104 B
    static bool attrDone = false;
    if (!attrDone) {
        cudaFuncSetAttribute(gemm_qkv_tc, cudaFuncAttributeMaxDynamicSharedMemorySize, GSMEM);
        cudaFuncSetAttribute(gemm_out_tc, cudaFuncAttributeMaxDynamicSharedMemorySize, GSMEM);
        cudaFuncSetAttribute(flash_attn_tc, cudaFuncAttributeMaxDynamicSharedMemorySize, fsmem);
        attrDone = true;
    }

    const int nW4 = DD * DD / 4;
    const int nX4 = BB * TT * DD / 4;

    convert_w4<<<dim3(nW4 / 256, 4), 256>>>(
        (const float4*)Wq, (const float4*)Wk, (const float4*)Wv, (const float4*)Wo,
        (u32*)Wqh, (u32*)Wql, (u32*)Wkh, (u32*)Wkl,
        (u32*)Wvh, (u32*)Wvl, (u32*)Woh, (u32*)Wol);
    convert_x3<<<dim3(nX4 / 256, 3), 256>>>(
        (const float4*)query, (const float4*)key, (const float4*)value,
        (u32*)I0h, (u32*)I0l, (u32*)I1h, (u32*)I1l, (u32*)I2h, (u32*)I2l);

    GJob jq = { I0h, I0l, Wqh, Wql, bq, Qh, Ql, 0.125f };
    GJob jk = { I1h, I1l, Wkh, Wkl, bk, Kh, Kl, 1.0f };
    GJob jv = { I2h, I2l, Wvh, Wvl, bv, Vh, Vl, 1.0f };
    gemm_qkv_tc<<<dim3(16, 32, 3), 256, GSMEM>>>(jq, jk, jv);

    dim3 fgrid(TT / 128, HH, BB);         // (16, 16, 2) = 512 CTAs
    flash_attn_tc<<<fgrid, 256, fsmem>>>(Qh, Ql, Kh, Kl, Vh, Vl, mask, Ch, Cl);

    gemm_out_tc<<<dim3(16, 32, 1), 256, GSMEM>>>(Ch, Cl, Woh, Wol, bo, out);
}

// round 15
// speedup vs baseline: 1.4108x; 1.3677x over previous
#include <cuda_runtime.h>
#include <cuda_bf16.h>
#include <cuda_fp16.h>
#include <math.h>

#define BB 2
#define TT 2048
#define DD 1024
#define HH 16
#define DK 64

typedef unsigned long long u64;
typedef unsigned int u32;

__device__ __forceinline__ void ldmx4(u32& r0, u32& r1, u32& r2, u32& r3, const void* p) {
    u32 addr = (u32)__cvta_generic_to_shared(p);
    asm volatile("ldmatrix.sync.aligned.m8n8.x4.shared.b16 {%0,%1,%2,%3},[%4];"
                 : "=r"(r0), "=r"(r1), "=r"(r2), "=r"(r3) : "r"(addr));
}
__device__ __forceinline__ void ldmx4t(u32& r0, u32& r1, u32& r2, u32& r3, const void* p) {
    u32 addr = (u32)__cvta_generic_to_shared(p);
    asm volatile("ldmatrix.sync.aligned.m8n8.x4.trans.shared.b16 {%0,%1,%2,%3},[%4];"
                 : "=r"(r0), "=r"(r1), "=r"(r2), "=r"(r3) : "r"(addr));
}
// bf16 MMA (projections)
__device__ __forceinline__ void mma16816(float* c, const u32* a, const u32* b) {
    asm("mma.sync.aligned.m16n8k16.row.col.f32.bf16.bf16.f32 "
        "{%0,%1,%2,%3},{%4,%5,%6,%7},{%8,%9},{%0,%1,%2,%3};"
        : "+f"(c[0]), "+f"(c[1]), "+f"(c[2]), "+f"(c[3])
        : "r"(a[0]), "r"(a[1]), "r"(a[2]), "r"(a[3]), "r"(b[0]), "r"(b[1]));
}
// fp16 MMA (attention)
__device__ __forceinline__ void mma16816h(float* c, const u32* a, const u32* b) {
    asm("mma.sync.aligned.m16n8k16.row.col.f32.f16.f16.f32 "
        "{%0,%1,%2,%3},{%4,%5,%6,%7},{%8,%9},{%0,%1,%2,%3};"
        : "+f"(c[0]), "+f"(c[1]), "+f"(c[2]), "+f"(c[3])
        : "r"(a[0]), "r"(a[1]), "r"(a[2]), "r"(a[3]), "r"(b[0]), "r"(b[1]));
}
__device__ __forceinline__ u32 packbf(float lo, float hi) {
    u32 r; asm("cvt.rn.satfinite.bf16x2.f32 %0,%1,%2;" : "=r"(r) : "f"(hi), "f"(lo));
    return r;
}
__device__ __forceinline__ u32 packhf(float lo, float hi) {
    u32 r; asm("cvt.rn.f16x2.f32 %0,%1,%2;" : "=r"(r) : "f"(hi), "f"(lo));
    return r;
}
__device__ __forceinline__ void cp16(u32 dst, const void* src) {
    asm volatile("cp.async.cg.shared.global [%0],[%1],16;" :: "r"(dst), "l"(src));
}
#define CP_COMMIT() asm volatile("cp.async.commit_group;")
#define CP_WAIT1()  asm volatile("cp.async.wait_group 1;")
#define CP_WAIT0()  asm volatile("cp.async.wait_group 0;")

// MUFU-free exp
__device__ __forceinline__ float fast_exp(float x) {
    float z = fmaxf(x * 1.4426950408889634f, -126.0f);
    float zi = z + 12582912.0f;
    float f = z - (zi - 12582912.0f);
    int n = __float_as_int(zi) - 0x4B400000;
    float p = 1.3333558e-3f;
    p = fmaf(p, f, 9.6181291e-3f);
    p = fmaf(p, f, 5.5504109e-2f);
    p = fmaf(p, f, 2.4022651e-1f);
    p = fmaf(p, f, 6.9314718e-1f);
    p = fmaf(p, f, 1.0f);
    return p * __int_as_float((n + 127) << 23);
}

// ---------------- scratch ----------------
__device__ __nv_bfloat16 g_I0h[BB*TT*DD], g_I0l[BB*TT*DD];
__device__ __nv_bfloat16 g_I1h[BB*TT*DD], g_I1l[BB*TT*DD];
__device__ __nv_bfloat16 g_I2h[BB*TT*DD], g_I2l[BB*TT*DD];
__device__ __nv_bfloat16 g_Wqh[DD*DD], g_Wql[DD*DD];
__device__ __nv_bfloat16 g_Wkh[DD*DD], g_Wkl[DD*DD];
__device__ __nv_bfloat16 g_Wvh[DD*DD], g_Wvl[DD*DD];
__device__ __nv_bfloat16 g_Woh[DD*DD], g_Wol[DD*DD];
__device__ __half g_Qf[BB*TT*DD], g_Kf[BB*TT*DD], g_Vf[BB*TT*DD];
__device__ __nv_bfloat16 g_Ch[BB*TT*DD], g_Cl[BB*TT*DD];

// ---------------------------------------------------------------------------
// fused converts
// ---------------------------------------------------------------------------
__device__ __forceinline__ void split_store(const float4 v, u32* H, u32* L, int i) {
    u32 h0 = packbf(v.x, v.y), h1 = packbf(v.z, v.w);
    u32 l0 = packbf(v.x - __int_as_float(h0 << 16), v.y - __int_as_float(h0 & 0xFFFF0000u));
    u32 l1 = packbf(v.z - __int_as_float(h1 << 16), v.w - __int_as_float(h1 & 0xFFFF0000u));
    *(uint2*)&H[i * 2] = make_uint2(h0, h1);
    *(uint2*)&L[i * 2] = make_uint2(l0, l1);
}

__global__ __launch_bounds__(256) void convert_x3(
    const float4* __restrict__ X0, const float4* __restrict__ X1,
    const float4* __restrict__ X2,
    u32* __restrict__ H0, u32* __restrict__ L0,
    u32* __restrict__ H1, u32* __restrict__ L1,
    u32* __restrict__ H2, u32* __restrict__ L2)
{
    const int i = blockIdx.x * 256 + threadIdx.x;
    const int y = blockIdx.y;
    const float4* X = (y == 0) ? X0 : (y == 1) ? X1 : X2;
    u32* H = (y == 0) ? H0 : (y == 1) ? H1 : H2;
    u32* L = (y == 0) ? L0 : (y == 1) ? L1 : L2;
    split_store(X[i], H, L, i);
}

__global__ __launch_bounds__(256) void convert_w4(
    const float4* __restrict__ W0, const float4* __restrict__ W1,
    const float4* __restrict__ W2, const float4* __restrict__ W3,
    u32* __restrict__ H0, u32* __restrict__ L0,
    u32* __restrict__ H1, u32* __restrict__ L1,
    u32* __restrict__ H2, u32* __restrict__ L2,
    u32* __restrict__ H3, u32* __restrict__ L3)
{
    const int i = blockIdx.x * 256 + threadIdx.x;
    const int y = blockIdx.y;
    const float4* W = (y == 0) ? W0 : (y == 1) ? W1 : (y == 2) ? W2 : W3;
    u32* H = (y == 0) ? H0 : (y == 1) ? H1 : (y == 2) ? H2 : H3;
    u32* L = (y == 0) ? L0 : (y == 1) ? L1 : (y == 2) ? L2 : L3;
    split_store(W[i], H, L, i);
}

// ---------------------------------------------------------------------------
// GEMM: CTA tile 128x64, warp 32x32, BK=32, 3-stage cp.async, 2 CTAs/SM.
// MODE 0: fp32 out.  MODE 1: fp16 out (scaled) for attention inputs.
// ---------------------------------------------------------------------------
#define GW 40
#define OFF_AH 0
#define OFF_AL (128 * GW)
#define OFF_BH (256 * GW)
#define OFF_BL (256 * GW + 64 * GW)
#define GSTAGE (384 * GW)
#define GSMEM  (3 * GSTAGE * 2)          // 92160 B

struct GJob {
    const __nv_bfloat16 *Xh, *Xl, *Wh, *Wl;
    const float* bias;
    __half* Yf16;
    float oscale;
};

template<int MODE>
__device__ __forceinline__ void gemm_body(
    char* smraw,
    const __nv_bfloat16* __restrict__ Xh, const __nv_bfloat16* __restrict__ Xl,
    const __nv_bfloat16* __restrict__ Wh, const __nv_bfloat16* __restrict__ Wl,
    const float* __restrict__ bias, float* __restrict__ Yf,
    __half* __restrict__ Yf16, float oscale)
{
    __nv_bfloat16* SM = (__nv_bfloat16*)smraw;
    const u32 smb = (u32)__cvta_generic_to_shared(smraw);

    const int tid  = threadIdx.x;
    const int lane = tid & 31;
    const int warp = tid >> 5;
    const int wr = (warp & 3) * 32;
    const int wc = (warp >> 2) * 32;
    const int rowBase = blockIdx.y * 128;
    const int colBase = blockIdx.x * 64;

    const int ar  = tid >> 1;
    const int ac0 = (tid & 1) * 2;
    const int br  = tid & 63;
    const int bc  = tid >> 6;
    const __nv_bfloat16* xh = Xh + (u64)(rowBase + ar) * 1024;
    const __nv_bfloat16* xl = Xl + (u64)(rowBase + ar) * 1024;
    const __nv_bfloat16* wh = Wh + (u64)(colBase + br) * 1024;
    const __nv_bfloat16* wl = Wl + (u64)(colBase + br) * 1024;

    const int a_r = (lane & 15);
    const int a_k = (lane >> 4) * 8;
    const int b_r = ((lane >> 4) << 3) + (lane & 7);
    const int b_k = ((lane >> 3) & 1) * 8;

    float acc[2][4][4];
    #pragma unroll
    for (int mt = 0; mt < 2; mt++)
        #pragma unroll
        for (int nt = 0; nt < 4; nt++)
            #pragma unroll
            for (int q = 0; q < 4; q++) acc[mt][nt][q] = 0.f;

    auto issue = [&](int kt) {
        const u32 sb = smb + (u32)((kt % 3) * GSTAGE) * 2;
        const int k0 = kt * 32;
        #pragma unroll
        for (int c = 0; c < 2; c++) {
            cp16(sb + (u32)(OFF_AH + ar * GW + (ac0 + c) * 8) * 2, xh + k0 + (ac0 + c) * 8);
            cp16(sb + (u32)(OFF_AL + ar * GW + (ac0 + c) * 8) * 2, xl + k0 + (ac0 + c) * 8);
        }
        cp16(sb + (u32)(OFF_BH + br * GW + bc * 8) * 2, wh + k0 + bc * 8);
        cp16(sb + (u32)(OFF_BL + br * GW + bc * 8) * 2, wl + k0 + bc * 8);
        CP_COMMIT();
    };

    issue(0);
    issue(1);

    for (int kt = 0; kt < 32; kt++) {
        if (kt < 31) CP_WAIT1(); else CP_WAIT0();
        __syncthreads();
        if (kt + 2 < 32) issue(kt + 2);

        const __nv_bfloat16* Ah = SM + (kt % 3) * GSTAGE;
        const __nv_bfloat16* Al = Ah + OFF_AL;
        const __nv_bfloat16* Bh = Ah + OFF_BH;
        const __nv_bfloat16* Bl = Ah + OFF_BL;

        #pragma unroll
        for (int ks = 0; ks < 32; ks += 16) {
            u32 ah[2][4], al[2][4], bh[2][4], bl[2][4];
            #pragma unroll
            for (int mt = 0; mt < 2; mt++) {
                ldmx4(ah[mt][0], ah[mt][1], ah[mt][2], ah[mt][3],
                      &Ah[(wr + mt*16 + a_r) * GW + ks + a_k]);
                ldmx4(al[mt][0], al[mt][1], al[mt][2], al[mt][3],
                      &Al[(wr + mt*16 + a_r) * GW + ks + a_k]);
            }
            #pragma unroll
            for (int p = 0; p < 2; p++) {
                ldmx4(bh[p][0], bh[p][1], bh[p][2], bh[p][3],
                      &Bh[(wc + p*16 + b_r) * GW + ks + b_k]);
                ldmx4(bl[p][0], bl[p][1], bl[p][2], bl[p][3],
                      &Bl[(wc + p*16 + b_r) * GW + ks + b_k]);
            }
            #pragma unroll
            for (int mt = 0; mt < 2; mt++)
                #pragma unroll
                for (int nt = 0; nt < 4; nt++)
                    mma16816(acc[mt][nt], ah[mt], &bh[nt >> 1][(nt & 1) * 2]);
            #pragma unroll
            for (int mt = 0; mt < 2; mt++)
                #pragma unroll
                for (int nt = 0; nt < 4; nt++)
                    mma16816(acc[mt][nt], ah[mt], &bl[nt >> 1][(nt & 1) * 2]);
            #pragma unroll
            for (int mt = 0; mt < 2; mt++)
                #pragma unroll
                for (int nt = 0; nt < 4; nt++)
                    mma16816(acc[mt][nt], al[mt], &bh[nt >> 1][(nt & 1) * 2]);
        }
    }

    const int crow = rowBase + wr + (lane >> 2);
    const int ccol = colBase + wc + (lane & 3) * 2;
    #pragma unroll
    for (int mt = 0; mt < 2; mt++)
        #pragma unroll
        for (int nt = 0; nt < 4; nt++) {
            const int row = crow + mt * 16;
            const int col = ccol + (nt >> 1) * 16 + (nt & 1) * 8;
            const float b0 = bias[col], b1 = bias[col + 1];
            float y00 = acc[mt][nt][0] + b0, y01 = acc[mt][nt][1] + b1;
            float y10 = acc[mt][nt][2] + b0, y11 = acc[mt][nt][3] + b1;
            if (MODE == 0) {
                Yf[(u64)row * 1024 + col]           = y00;
                Yf[(u64)row * 1024 + col + 1]       = y01;
                Yf[(u64)(row + 8) * 1024 + col]     = y10;
                Yf[(u64)(row + 8) * 1024 + col + 1] = y11;
            } else {
                u32 p0 = packhf(y00 * oscale, y01 * oscale);
                u32 p1 = packhf(y10 * oscale, y11 * oscale);
                *(u32*)&Yf16[(u64)row * 1024 + col]       = p0;
                *(u32*)&Yf16[(u64)(row + 8) * 1024 + col] = p1;
            }
        }
}

__global__ __launch_bounds__(256, 2) void gemm_qkv_tc(GJob j0, GJob j1, GJob j2)
{
    extern __shared__ char smraw[];
    const GJob& j = (blockIdx.z == 0) ? j0 : (blockIdx.z == 1) ? j1 : j2;
    gemm_body<1>(smraw, j.Xh, j.Xl, j.Wh, j.Wl, j.bias, nullptr, j.Yf16, j.oscale);
}

__global__ __launch_bounds__(256, 2) void gemm_out_tc(
    const __nv_bfloat16* __restrict__ Xh, const __nv_bfloat16* __restrict__ Xl,
    const __nv_bfloat16* __restrict__ Wh, const __nv_bfloat16* __restrict__ Wl,
    const float* __restrict__ bias, float* __restrict__ Yf)
{
    extern __shared__ char smraw[];
    gemm_body<0>(smraw, Xh, Xl, Wh, Wl, bias, Yf, nullptr, 1.0f);
}

// ---------------------------------------------------------------------------
// Flash attention fp16 single-product: 256 threads, Q-tile 128, key-tile 64,
// 2-stage KV, 2 CTAs/SM.
// ---------------------------------------------------------------------------
#define KST 72
#define QARR (128 * KST)                // fp16 elements (Q)
#define FARR (64 * KST)                 // fp16 elements (K or V)
#define FSTAGE (2 * FARR)               // K,V per stage

__global__ __launch_bounds__(256, 2) void flash_attn_tc(
    const __half* __restrict__ Qfg, const __half* __restrict__ Kfg,
    const __half* __restrict__ Vfg, const int* __restrict__ mask,
    __nv_bfloat16* __restrict__ Ch, __nv_bfloat16* __restrict__ Cl)
{
    extern __shared__ char smraw[];
    __half* Qf_s = (__half*)smraw;
    __half* KV   = Qf_s + QARR;
    float* mb = (float*)(KV + 2 * FSTAGE);
    const u32 kvb = (u32)__cvta_generic_to_shared(KV);

    const int tid  = threadIdx.x;
    const int lane = tid & 31;
    const int warp = tid >> 5;       // 0..7
    const int wr   = warp * 16;
    const int q0 = blockIdx.x * 128;
    const int h  = blockIdx.y;
    const int b  = blockIdx.z;

    const int a_r = (lane & 15);
    const int a_k = (lane >> 4) * 8;
    const int b_r = ((lane >> 4) << 3) + (lane & 7);
    const int b_k = ((lane >> 3) & 1) * 8;
    const int v_r = (((lane >> 3) & 1) << 3) + (lane & 7);
    const int v_c = (lane >> 4) * 8;

    // Q staging: 128 rows x 64 fp16, 2 threads/row
    {
        const int row = tid >> 1;
        const int half = (tid & 1) * 32;
        const u64 gro = (u64)(b * TT + q0 + row) * DD + h * DK + half;
        #pragma unroll
        for (int c = 0; c < 4; c++)
            *(uint4*)&Qf_s[row * KST + half + c * 8] = *(const uint4*)&Qfg[gro + c * 8];
    }
    __syncthreads();
    u32 qa[4][4];
    #pragma unroll
    for (int ks = 0; ks < 4; ks++)
        ldmx4(qa[ks][0], qa[ks][1], qa[ks][2], qa[ks][3],
              &Qf_s[(wr + a_r) * KST + ks * 16 + a_k]);

    // KV cp.async: 128 threads per array; thread loads 4 chunks of one row-half
    const int la = tid >> 7;                 // 0:K 1:V
    const int r0 = (tid & 127) >> 1;         // row 0..63
    const int c0 = (tid & 1) * 4;            // chunk base 0 or 4
    const __half* sp = (la == 0) ? Kfg : Vfg;
    const u32 dbase = kvb + (u32)(la * FARR + r0 * KST) * 2;

    auto issueKV = [&](int t, int buf) {
        const int s0 = t * 64;
        const __half* sbase = sp + (u64)(b * TT + s0 + r0) * DD + h * DK;
        #pragma unroll
        for (int c = 0; c < 4; c++)
            cp16(dbase + (u32)(buf * FSTAGE + (c0 + c) * 8) * 2, sbase + (c0 + c) * 8);
        if (tid < 64)
            mb[buf * 64 + tid] = (mask[b * TT + s0 + tid] != 0) ? 0.f : -1e30f;
        CP_COMMIT();
    };

    issueKV(0, 0);
    issueKV(1, 1);

    float m0 = -1e30f, m1 = -1e30f, l0 = 0.f, l1 = 0.f;
    float o[8][4];
    #pragma unroll
    for (int nt = 0; nt < 8; nt++)
        #pragma unroll
        for (int q = 0; q < 4; q++) o[nt][q] = 0.f;

    for (int t = 0; t < 32; t++) {
        if (t < 31) CP_WAIT1(); else CP_WAIT0();
        __syncthreads();
        const int buf = t & 1;
        const __half* Kfs = KV + buf * FSTAGE;
        const __half* Vfs = Kfs + FARR;
        const float* mbp = mb + buf * 64;

        // ---- S = Qs @ K^T (64 keys, single product) ----
        float s[8][4];
        #pragma unroll
        for (int nt = 0; nt < 8; nt++)
            #pragma unroll
            for (int q = 0; q < 4; q++) s[nt][q] = 0.f;

        #pragma unroll
        for (int np = 0; np < 4; np++) {
            #pragma unroll
            for (int ks = 0; ks < 4; ks++) {
                u32 kf[4];
                ldmx4(kf[0], kf[1], kf[2], kf[3],
                      &Kfs[(np*16 + b_r) * KST + ks*16 + b_k]);
                mma16816h(s[2*np],   qa[ks], &kf[0]);
                mma16816h(s[2*np+1], qa[ks], &kf[2]);
            }
        }

        // ---- mask + online softmax ----
        float mx0 = m0, mx1 = m1;
        #pragma unroll
        for (int nt = 0; nt < 8; nt++) {
            float2 mbv = *(const float2*)&mbp[nt*8 + (lane & 3)*2];
            s[nt][0] += mbv.x; s[nt][1] += mbv.y;
            s[nt][2] += mbv.x; s[nt][3] += mbv.y;
            mx0 = fmaxf(mx0, fmaxf(s[nt][0], s[nt][1]));
            mx1 = fmaxf(mx1, fmaxf(s[nt][2], s[nt][3]));
        }
        mx0 = fmaxf(mx0, __shfl_xor_sync(0xffffffffu, mx0, 1));
        mx0 = fmaxf(mx0, __shfl_xor_sync(0xffffffffu, mx0, 2));
        mx1 = fmaxf(mx1, __shfl_xor_sync(0xffffffffu, mx1, 1));
        mx1 = fmaxf(mx1, __shfl_xor_sync(0xffffffffu, mx1, 2));
        const float sc0 = fast_exp(m0 - mx0);
        const float sc1 = fast_exp(m1 - mx1);
        m0 = mx0; m1 = mx1;
        float rs0 = 0.f, rs1 = 0.f;
        #pragma unroll
        for (int nt = 0; nt < 8; nt++) {
            s[nt][0] = fast_exp(s[nt][0] - mx0);
            s[nt][1] = fast_exp(s[nt][1] - mx0);
            s[nt][2] = fast_exp(s[nt][2] - mx1);
            s[nt][3] = fast_exp(s[nt][3] - mx1);
            rs0 += s[nt][0] + s[nt][1];
            rs1 += s[nt][2] + s[nt][3];
        }
        rs0 += __shfl_xor_sync(0xffffffffu, rs0, 1);
        rs0 += __shfl_xor_sync(0xffffffffu, rs0, 2);
        rs1 += __shfl_xor_sync(0xffffffffu, rs1, 1);
        rs1 += __shfl_xor_sync(0xffffffffu, rs1, 2);
        l0 = l0 * sc0 + rs0;
        l1 = l1 * sc1 + rs1;
        #pragma unroll
        for (int nt = 0; nt < 8; nt++) {
            o[nt][0] *= sc0; o[nt][1] *= sc0;
            o[nt][2] *= sc1; o[nt][3] *= sc1;
        }

        // ---- O += P @ V (64 keys, single product) ----
        #pragma unroll
        for (int kc = 0; kc < 4; kc++) {
            u32 pa[4];
            pa[0] = packhf(s[2*kc][0],   s[2*kc][1]);
            pa[1] = packhf(s[2*kc][2],   s[2*kc][3]);
            pa[2] = packhf(s[2*kc+1][0], s[2*kc+1][1]);
            pa[3] = packhf(s[2*kc+1][2], s[2*kc+1][3]);
            #pragma unroll
            for (int nb = 0; nb < 4; nb++) {
                u32 vf[4];
                ldmx4t(vf[0], vf[1], vf[2], vf[3],
                       &Vfs[(kc*16 + v_r) * KST + nb*16 + v_c]);
                mma16816h(o[2*nb],   pa, &vf[0]);
                mma16816h(o[2*nb+1], pa, &vf[2]);
            }
        }

        __syncthreads();
        if (t + 2 < 32) issueKV(t + 2, buf);
    }

    // epilogue: C as bf16 hi/lo (input to output projection)
    const float inv0 = 1.f / l0;
    const float inv1 = 1.f / l1;
    const int row0 = b * TT + q0 + wr + (lane >> 2);
    #pragma unroll
    for (int nt = 0; nt < 8; nt++) {
        const int dcol = h * DK + (nt >> 1) * 16 + (nt & 1) * 8 + (lane & 3) * 2;
        float y00 = o[nt][0] * inv0, y01 = o[nt][1] * inv0;
        float y10 = o[nt][2] * inv1, y11 = o[nt][3] * inv1;
        u32 h0 = packbf(y00, y01);
        u32 l0p = packbf(y00 - __int_as_float(h0 << 16),
                         y01 - __int_as_float(h0 & 0xFFFF0000u));
        u32 h1 = packbf(y10, y11);
        u32 l1p = packbf(y10 - __int_as_float(h1 << 16),
                         y11 - __int_as_float(h1 & 0xFFFF0000u));
        *(u32*)&Ch[(u64)row0 * DD + dcol]       = h0;
        *(u32*)&Cl[(u64)row0 * DD + dcol]       = l0p;
        *(u32*)&Ch[(u64)(row0 + 8) * DD + dcol] = h1;
        *(u32*)&Cl[(u64)(row0 + 8) * DD + dcol] = l1p;
    }
}

// ---------------------------------------------------------------------------
extern "C" void kernel_launch(void* const* d_in, const int* in_sizes, int n_in,
                              void* d_out, int out_size)
{
    const float* query = (const float*)d_in[0];
    const float* key   = (const float*)d_in[1];
    const float* value = (const float*)d_in[2];
    const int*   mask  = (const int*)d_in[3];
    const float* Wq = (const float*)d_in[4];
    const float* bq = (const float*)d_in[5];
    const float* Wk = (const float*)d_in[6];
    const float* bk = (const float*)d_in[7];
    const float* Wv = (const float*)d_in[8];
    const float* bv = (const float*)d_in[9];
    const float* Wo = (const float*)d_in[10];
    const float* bo = (const float*)d_in[11];
    float* out = (float*)d_out;

    __nv_bfloat16 *I0h,*I0l,*I1h,*I1l,*I2h,*I2l;
    __nv_bfloat16 *Wqh,*Wql,*Wkh,*Wkl,*Wvh,*Wvl,*Woh,*Wol;
    __nv_bfloat16 *Ch,*Cl;
    __half *Qf,*Kf,*Vf;
    cudaGetSymbolAddress((void**)&I0h, g_I0h);  cudaGetSymbolAddress((void**)&I0l, g_I0l);
    cudaGetSymbolAddress((void**)&I1h, g_I1h);  cudaGetSymbolAddress((void**)&I1l, g_I1l);
    cudaGetSymbolAddress((void**)&I2h, g_I2h);  cudaGetSymbolAddress((void**)&I2l, g_I2l);
    cudaGetSymbolAddress((void**)&Wqh, g_Wqh);  cudaGetSymbolAddress((void**)&Wql, g_Wql);
    cudaGetSymbolAddress((void**)&Wkh, g_Wkh);  cudaGetSymbolAddress((void**)&Wkl, g_Wkl);
    cudaGetSymbolAddress((void**)&Wvh, g_Wvh);  cudaGetSymbolAddress((void**)&Wvl, g_Wvl);
    cudaGetSymbolAddress((void**)&Woh, g_Woh);  cudaGetSymbolAddress((void**)&Wol, g_Wol);
    cudaGetSymbolAddress((void**)&Qf, g_Qf);    cudaGetSymbolAddress((void**)&Kf, g_Kf);
    cudaGetSymbolAddress((void**)&Vf, g_Vf);
    cudaGetSymbolAddress((void**)&Ch, g_Ch);    cudaGetSymbolAddress((void**)&Cl, g_Cl);

    const int fsmem = (QARR + 2*FSTAGE) * 2 + 2*64*4;  // 55,808 B
    static bool attrDone = false;
    if (!attrDone) {
        cudaFuncSetAttribute(gemm_qkv_tc, cudaFuncAttributeMaxDynamicSharedMemorySize, GSMEM);
        cudaFuncSetAttribute(gemm_out_tc, cudaFuncAttributeMaxDynamicSharedMemorySize, GSMEM);
        cudaFuncSetAttribute(flash_attn_tc, cudaFuncAttributeMaxDynamicSharedMemorySize, fsmem);
        attrDone = true;
    }

    const int nW4 = DD * DD / 4;
    const int nX4 = BB * TT * DD / 4;

    convert_w4<<<dim3(nW4 / 256, 4), 256>>>(
        (const float4*)Wq, (const float4*)Wk, (const float4*)Wv, (const float4*)Wo,
        (u32*)Wqh, (u32*)Wql, (u32*)Wkh, (u32*)Wkl,
        (u32*)Wvh, (u32*)Wvl, (u32*)Woh, (u32*)Wol);
    convert_x3<<<dim3(nX4 / 256, 3), 256>>>(
        (const float4*)query, (const float4*)key, (const float4*)value,
        (u32*)I0h, (u32*)I0l, (u32*)I1h, (u32*)I1l, (u32*)I2h, (u32*)I2l);

    GJob jq = { I0h, I0l, Wqh, Wql, bq, Qf, 0.125f };
    GJob jk = { I1h, I1l, Wkh, Wkl, bk, Kf, 1.0f };
    GJob jv = { I2h, I2l, Wvh, Wvl, bv, Vf, 1.0f };
    gemm_qkv_tc<<<dim3(16, 32, 3), 256, GSMEM>>>(jq, jk, jv);

    dim3 fgrid(TT / 128, HH, BB);         // (16, 16, 2) = 512 CTAs
    flash_attn_tc<<<fgrid, 256, fsmem>>>(Qf, Kf, Vf, mask, Ch, Cl);

    gemm_out_tc<<<dim3(16, 32, 1), 256, GSMEM>>>(Ch, Cl, Woh, Wol, bo, out);
}